// round 9
// baseline (speedup 1.0000x reference)
#include <cuda_runtime.h>
#include <math.h>

#define B_  32
#define H_  512
#define W_  512
#define DEG 0.017453292519943295f
#define NT  256     // 8 warps; warp w handles rows [w*4, w*4+4) of a 32x32 tile

__device__ float g_params[B_ * 32];

__device__ __forceinline__ float frcp_nr(float x) {
    float y;
    asm("rcp.approx.f32 %0, %1;" : "=f"(y) : "f"(x));
    return y * fmaf(-x, y, 2.0f);   // one Newton step -> ~1 ulp
}
__device__ __forceinline__ float flg2(float x) {
    float y;
    asm("lg2.approx.f32 %0, %1;" : "=f"(y) : "f"(x));
    return y;
}
__device__ __forceinline__ float fex2(float x) {
    float y;
    asm("ex2.approx.f32 %0, %1;" : "=f"(y) : "f"(x));
    return y;
}

__device__ __forceinline__ void mat3_mul(const float* A, const float* Bm, float* C) {
#pragma unroll
    for (int i = 0; i < 3; i++)
#pragma unroll
        for (int j = 0; j < 3; j++) {
            float s = 0.f;
#pragma unroll
            for (int k = 0; k < 3; k++) s += A[i * 3 + k] * Bm[k * 3 + j];
            C[i * 3 + j] = s;
        }
}

__global__ void param_kernel(const float* __restrict__ geom_u,
                             const float* __restrict__ color_u,
                             const float* __restrict__ cutout_u) {
    int b = threadIdx.x;
    if (b >= B_) return;

    const float* g = geom_u + b * 8;
    float flip = g[0] > 0.5f ? -1.f : 1.f;
    float tilt = (g[1] * 2.f - 1.f) * (15.f * DEG);
    float pan  = (g[2] * 2.f - 1.f) * (15.f * DEG);
    float rot  = (g[3] * 2.f - 1.f) * (15.f * DEG);
    float sc   = 1.f + (g[4] * 2.f - 1.f) * 0.1f;
    float tx   = (g[5] * 2.f - 1.f) * 0.2f;
    float ty   = (g[6] * 2.f - 1.f) * 0.2f;

    float F[9]  = {flip, 0, 0, 0, 1, 0, 0, 0, 1};
    float ct = cosf(tilt), st = sinf(tilt);
    float Rx[9] = {1, 0, 0, 0, ct, -st, 0, st, ct};
    float cp = cosf(pan), sp = sinf(pan);
    float Ry[9] = {cp, 0, sp, 0, 1, 0, -sp, 0, cp};
    float cr = cosf(rot), sr = sinf(rot);
    float RS[9] = {sc * cr, -sc * sr, 0, sc * sr, sc * cr, 0, 0, 0, 1};
    float T[9]  = {1, 0, tx, 0, 1, ty, 0, 0, 1};

    float t0[9], t1[9], t2[9], M[9];
    mat3_mul(Ry, F, t0);
    mat3_mul(Rx, t0, t1);
    mat3_mul(RS, t1, t2);
    mat3_mul(T, t2, M);

    const float* c = color_u + b * 4;
    float theta = (c[0] * 2.f - 1.f) * (10.f * DEG);
    float cth = cosf(theta), sth = sinf(theta);
    const float a = 0.5773502691896258f;
    float K[9] = {0, -a, a, a, 0, -a, -a, a, 0};
    float Rh[9];
#pragma unroll
    for (int i = 0; i < 3; i++)
#pragma unroll
        for (int j = 0; j < 3; j++)
            Rh[i * 3 + j] = cth * (i == j ? 1.f : 0.f) + sth * K[i * 3 + j] +
                            (1.f - cth) * (1.f / 3.f);
    float sat = 1.f + (c[1] * 2.f - 1.f) * 0.4f;
    const float lum[3] = {0.299f, 0.587f, 0.114f};
    float Sm[9];
#pragma unroll
    for (int i = 0; i < 3; i++)
#pragma unroll
        for (int j = 0; j < 3; j++)
            Sm[i * 3 + j] = sat * (i == j ? 1.f : 0.f) + (1.f - sat) * lum[j];
    float bright = 1.f + (c[2] * 2.f - 1.f) * 0.1f;
    float Mc[9];
    mat3_mul(Sm, Rh, Mc);
#pragma unroll
    for (int i = 0; i < 9; i++) Mc[i] *= bright;
    float gamma = 1.f + (c[3] * 2.f - 1.f) * 0.2f;

    const float* cu = cutout_u + b * 5;
    float* p = g_params + b * 32;
#pragma unroll
    for (int i = 0; i < 9; i++) p[i] = M[i];
    p[9] = gamma;
#pragma unroll
    for (int i = 0; i < 9; i++) p[10 + i] = Mc[i];
    p[19] = (cu[0] < 0.5f) ? 1.f : 0.f;
    p[20] = cu[1];
    p[21] = cu[2];
    p[22] = (0.3f + 0.2f * cu[3]) * 0.5f;
    p[23] = (0.3f + 0.2f * cu[4]) * 0.5f;
}

__global__ __launch_bounds__(NT, 6) void augment_main(
    const float* __restrict__ images, float* __restrict__ out) {
    __shared__ float spm[24];

    int b   = blockIdx.z;
    int tid = threadIdx.x;
    if (tid < 24) spm[tid] = g_params[b * 32 + tid];
    __syncthreads();

    int lane = tid & 31;
    int w    = tid >> 5;
    int jx   = (blockIdx.x << 5) + lane;       // x (consecutive across warp!)
    int iy0  = (blockIdx.y << 5) + (w << 2);   // first of 4 rows

    float m0 = spm[0], m1 = spm[1], m2 = spm[2];
    float m3 = spm[3], m4 = spm[4], m5 = spm[5];
    float m6 = spm[6], m7 = spm[7], m8 = spm[8];
    float gamma = spm[9];
    float c0 = spm[10], c1 = spm[11], c2 = spm[12];
    float c3 = spm[13], c4 = spm[14], c5 = spm[15];
    float c6 = spm[16], c7 = spm[17], c8 = spm[18];
    float capply = spm[19], ccx = spm[20], ccy = spm[21];
    float cwh = spm[22], chh = spm[23];

    const float cc = 2.f / 511.f;
    float X = (float)jx * cc - 1.f;
    float sxX = fmaf(m0, X, m2);
    float syX = fmaf(m3, X, m5);
    float szX = fmaf(m6, X, m8);

    float gx = (float)jx * (1.f / 511.f);
    bool cutx = (capply != 0.f) & (fabsf(gx - ccx) < cwh);

    int bOff = b << 18;
    int outBase = ((bOff + (iy0 << 9)) + jx) * 3;

#pragma unroll
    for (int k = 0; k < 4; k++) {
        int iy = iy0 + k;
        float Y = (float)iy * cc - 1.f;

        float sx = fmaf(m1, Y, sxX);
        float sy = fmaf(m4, Y, syX);
        float sz = fmaf(m7, Y, szX);
        float inv = frcp_nr(sz);
        float px = fmaf(sx * inv, 255.5f, 255.5f);
        float py = fmaf(sy * inv, 255.5f, 255.5f);

        bool valid = (px >= 0.f) & (px <= 511.f) & (py >= 0.f) & (py <= 511.f);
        int x0 = min(max(__float2int_rd(px), 0), 511);
        int y0 = min(max(__float2int_rd(py), 0), 511);
        float wx = px - (float)x0;
        float wy = py - (float)y0;
        int dx3 = (x0 < 511) ? 3 : 0;
        int dyW = (y0 < 511) ? (W_ * 3) : 0;

        const float* A  = images + (bOff + (y0 << 9) + x0) * 3;
        const float* Bt = A + dyW;

        // own x0-taps only: 6 loads
        float a00 = __ldg(A + 0),  a01 = __ldg(A + 1),  a02 = __ldg(A + 2);
        float d00 = __ldg(Bt + 0), d01 = __ldg(Bt + 1), d02 = __ldg(Bt + 2);

        // neighbor lane holds our x1-taps when its x0 == our x0+1
        int xn = __shfl_down_sync(0xffffffffu, x0, 1);
        int yn = __shfl_down_sync(0xffffffffu, y0, 1);
        bool ok = (lane < 31) & (xn == x0 + 1) & (yn == y0);

        float b00 = __shfl_down_sync(0xffffffffu, a00, 1);
        float b01 = __shfl_down_sync(0xffffffffu, a01, 1);
        float b02 = __shfl_down_sync(0xffffffffu, a02, 1);
        float e00 = __shfl_down_sync(0xffffffffu, d00, 1);
        float e01 = __shfl_down_sync(0xffffffffu, d01, 1);
        float e02 = __shfl_down_sync(0xffffffffu, d02, 1);

        if (!ok) {  // predicated fallback loads (no wavefronts on ok lanes)
            b00 = __ldg(A + dx3 + 0);
            b01 = __ldg(A + dx3 + 1);
            b02 = __ldg(A + dx3 + 2);
            e00 = __ldg(Bt + dx3 + 0);
            e01 = __ldg(Bt + dx3 + 1);
            e02 = __ldg(Bt + dx3 + 2);
        }

        float omx = 1.f - wx, omy = 1.f - wy;
        float w00 = omx * omy, w01 = wx * omy, w10 = omx * wy, w11 = wx * wy;
        float vm = valid ? 1.f : 0.f;

        float r0 = a00 * w00 + b00 * w01 + d00 * w10 + e00 * w11;
        float r1 = a01 * w00 + b01 * w01 + d01 * w10 + e01 * w11;
        float r2 = a02 * w00 + b02 * w01 + d02 * w10 + e02 * w11;
        r0 = fminf(r0 * vm, 1.f);   // taps/weights >= 0: lower clamp redundant
        r1 = fminf(r1 * vm, 1.f);
        r2 = fminf(r2 * vm, 1.f);
        r0 = fex2(gamma * flg2(r0));   // 0 -> ex2(-inf) = 0 == 0^g
        r1 = fex2(gamma * flg2(r1));
        r2 = fex2(gamma * flg2(r2));

        float o0 = c0 * r0 + c1 * r1 + c2 * r2;
        float o1 = c3 * r0 + c4 * r1 + c5 * r2;
        float o2 = c6 * r0 + c7 * r1 + c8 * r2;
        o0 = fminf(fmaxf(o0, 0.f), 1.f);
        o1 = fminf(fmaxf(o1, 0.f), 1.f);
        o2 = fminf(fmaxf(o2, 0.f), 1.f);

        float gy = (float)iy * (1.f / 511.f);
        bool cut = cutx & (fabsf(gy - ccy) < chh);
        if (cut) { o0 = 0.f; o1 = 0.f; o2 = 0.f; }

        float* op = out + outBase + k * (W_ * 3);
        op[0] = o0;
        op[1] = o1;
        op[2] = o2;
    }
}

extern "C" void kernel_launch(void* const* d_in, const int* in_sizes, int n_in,
                              void* d_out, int out_size) {
    const float* images   = (const float*)d_in[0];
    const float* geom_u   = (const float*)d_in[1];
    const float* color_u  = (const float*)d_in[2];
    const float* cutout_u = (const float*)d_in[3];
    float* out = (float*)d_out;

    param_kernel<<<1, 32>>>(geom_u, color_u, cutout_u);
    dim3 grid(W_ / 32, H_ / 32, B_);
    augment_main<<<grid, NT>>>(images, out);
}

// round 10
// speedup vs baseline: 1.0929x; 1.0929x over previous
#include <cuda_runtime.h>
#include <math.h>

#define B_  32
#define H_  512
#define W_  512
#define DEG 0.017453292519943295f
#define NT  256     // 8 warps; warp w handles rows [w*4, w*4+4) of a 32x32 tile

// per-batch: M[9], gamma, Mc[9], cutx0? -> now pixel-space cutout consts
// layout: 0..8 M, 9 gamma, 10..18 Mc, 19 ccx_px, 20 cwh_px, 21 ccy_px, 22 chh_px
__device__ float g_params[B_ * 32];

__device__ __forceinline__ float frcp_nr(float x) {
    float y;
    asm("rcp.approx.f32 %0, %1;" : "=f"(y) : "f"(x));
    return y * fmaf(-x, y, 2.0f);   // one Newton step -> ~1 ulp
}
__device__ __forceinline__ float flg2(float x) {
    float y;
    asm("lg2.approx.f32 %0, %1;" : "=f"(y) : "f"(x));
    return y;
}
__device__ __forceinline__ float fex2(float x) {
    float y;
    asm("ex2.approx.f32 %0, %1;" : "=f"(y) : "f"(x));
    return y;
}

__device__ __forceinline__ void mat3_mul(const float* A, const float* Bm, float* C) {
#pragma unroll
    for (int i = 0; i < 3; i++)
#pragma unroll
        for (int j = 0; j < 3; j++) {
            float s = 0.f;
#pragma unroll
            for (int k = 0; k < 3; k++) s += A[i * 3 + k] * Bm[k * 3 + j];
            C[i * 3 + j] = s;
        }
}

__global__ void param_kernel(const float* __restrict__ geom_u,
                             const float* __restrict__ color_u,
                             const float* __restrict__ cutout_u) {
    int b = threadIdx.x;
    if (b >= B_) return;

    const float* g = geom_u + b * 8;
    float flip = g[0] > 0.5f ? -1.f : 1.f;
    float tilt = (g[1] * 2.f - 1.f) * (15.f * DEG);
    float pan  = (g[2] * 2.f - 1.f) * (15.f * DEG);
    float rot  = (g[3] * 2.f - 1.f) * (15.f * DEG);
    float sc   = 1.f + (g[4] * 2.f - 1.f) * 0.1f;
    float tx   = (g[5] * 2.f - 1.f) * 0.2f;
    float ty   = (g[6] * 2.f - 1.f) * 0.2f;

    float F[9]  = {flip, 0, 0, 0, 1, 0, 0, 0, 1};
    float ct = cosf(tilt), st = sinf(tilt);
    float Rx[9] = {1, 0, 0, 0, ct, -st, 0, st, ct};
    float cp = cosf(pan), sp = sinf(pan);
    float Ry[9] = {cp, 0, sp, 0, 1, 0, -sp, 0, cp};
    float cr = cosf(rot), sr = sinf(rot);
    float RS[9] = {sc * cr, -sc * sr, 0, sc * sr, sc * cr, 0, 0, 0, 1};
    float T[9]  = {1, 0, tx, 0, 1, ty, 0, 0, 1};

    float t0[9], t1[9], t2[9], M[9];
    mat3_mul(Ry, F, t0);
    mat3_mul(Rx, t0, t1);
    mat3_mul(RS, t1, t2);
    mat3_mul(T, t2, M);

    const float* c = color_u + b * 4;
    float theta = (c[0] * 2.f - 1.f) * (10.f * DEG);
    float cth = cosf(theta), sth = sinf(theta);
    const float a = 0.5773502691896258f;
    float K[9] = {0, -a, a, a, 0, -a, -a, a, 0};
    float Rh[9];
#pragma unroll
    for (int i = 0; i < 3; i++)
#pragma unroll
        for (int j = 0; j < 3; j++)
            Rh[i * 3 + j] = cth * (i == j ? 1.f : 0.f) + sth * K[i * 3 + j] +
                            (1.f - cth) * (1.f / 3.f);
    float sat = 1.f + (c[1] * 2.f - 1.f) * 0.4f;
    const float lum[3] = {0.299f, 0.587f, 0.114f};
    float Sm[9];
#pragma unroll
    for (int i = 0; i < 3; i++)
#pragma unroll
        for (int j = 0; j < 3; j++)
            Sm[i * 3 + j] = sat * (i == j ? 1.f : 0.f) + (1.f - sat) * lum[j];
    float bright = 1.f + (c[2] * 2.f - 1.f) * 0.1f;
    float Mc[9];
    mat3_mul(Sm, Rh, Mc);
#pragma unroll
    for (int i = 0; i < 9; i++) Mc[i] *= bright;
    float gamma = 1.f + (c[3] * 2.f - 1.f) * 0.2f;

    const float* cu = cutout_u + b * 5;
    bool apply = (cu[0] < 0.5f);
    float* p = g_params + b * 32;
#pragma unroll
    for (int i = 0; i < 9; i++) p[i] = M[i];
    p[9] = gamma;
#pragma unroll
    for (int i = 0; i < 9; i++) p[10 + i] = Mc[i];
    // pixel-space cutout: |j - ccx*511| < cwh*511  (width disabled if !apply)
    p[19] = cu[1] * 511.f;
    p[20] = apply ? (0.3f + 0.2f * cu[3]) * 0.5f * 511.f : -1.f; // neg -> never cut
    p[21] = cu[2] * 511.f;
    p[22] = (0.3f + 0.2f * cu[4]) * 0.5f * 511.f;
}

__global__ __launch_bounds__(NT, 6) void augment_main(
    const float* __restrict__ images, float* __restrict__ out) {
    __shared__ float spm[24];

    int b   = blockIdx.z;
    int tid = threadIdx.x;
    if (tid < 24) spm[tid] = g_params[b * 32 + tid];
    __syncthreads();

    int lane = tid & 31;
    int w    = tid >> 5;
    int jx   = (blockIdx.x << 5) + lane;       // x (consecutive across warp)
    int iy0  = (blockIdx.y << 5) + (w << 2);   // first of 4 rows

    float m0 = spm[0], m1 = spm[1], m2 = spm[2];
    float m3 = spm[3], m4 = spm[4], m5 = spm[5];
    float m6 = spm[6], m7 = spm[7], m8 = spm[8];
    float gamma = spm[9];
    float c0 = spm[10], c1 = spm[11], c2 = spm[12];
    float c3 = spm[13], c4 = spm[14], c5 = spm[15];
    float c6 = spm[16], c7 = spm[17], c8 = spm[18];
    float ccx_px = spm[19], cwh_px = spm[20];
    float ccy_px = spm[21], chh_px = spm[22];

    const float cc = 2.f / 511.f;
    float X = (float)jx * cc - 1.f;
    float sxX = fmaf(m0, X, m2);
    float syX = fmaf(m3, X, m5);
    float szX = fmaf(m6, X, m8);

    bool cutx = fabsf((float)jx - ccx_px) < cwh_px;   // false if cwh_px < 0

    int bOff = b << 18;
    int outBase = ((bOff + (iy0 << 9)) + jx) * 3;

    float Y   = (float)iy0 * cc - 1.f;
    float fiy = (float)iy0;

#pragma unroll
    for (int k = 0; k < 4; k++) {
        float sx = fmaf(m1, Y, sxX);
        float sy = fmaf(m4, Y, syX);
        float sz = fmaf(m7, Y, szX);
        float inv = frcp_nr(sz);
        float px = fmaf(sx * inv, 255.5f, 255.5f);
        float py = fmaf(sy * inv, 255.5f, 255.5f);

        bool valid = (px >= 0.f) & (px <= 511.f) & (py >= 0.f) & (py <= 511.f);
        int x0 = min(max(__float2int_rd(px), 0), 511);
        int y0 = min(max(__float2int_rd(py), 0), 511);
        float wx = px - (float)x0;
        float wy = py - (float)y0;
        int dx3 = (x0 < 511) ? 3 : 0;
        int dyW = (y0 < 511) ? (W_ * 3) : 0;

        const float* A  = images + (bOff + (y0 << 9) + x0) * 3;
        const float* Bt = A + dyW;

        float a00 = __ldg(A + 0),        a01 = __ldg(A + 1),        a02 = __ldg(A + 2);
        float b00 = __ldg(A + dx3 + 0),  b01 = __ldg(A + dx3 + 1),  b02 = __ldg(A + dx3 + 2);
        float d00 = __ldg(Bt + 0),       d01 = __ldg(Bt + 1),       d02 = __ldg(Bt + 2);
        float e00 = __ldg(Bt + dx3 + 0), e01 = __ldg(Bt + dx3 + 1), e02 = __ldg(Bt + dx3 + 2);

        float omx = 1.f - wx, omy = 1.f - wy;
        float w00 = omx * omy, w01 = wx * omy, w10 = omx * wy, w11 = wx * wy;
        float vm = valid ? 1.f : 0.f;

        float r0 = a00 * w00 + b00 * w01 + d00 * w10 + e00 * w11;
        float r1 = a01 * w00 + b01 * w01 + d01 * w10 + e01 * w11;
        float r2 = a02 * w00 + b02 * w01 + d02 * w10 + e02 * w11;
        r0 = __saturatef(r0 * vm);   // taps >= 0; sat == clamp[0,1]
        r1 = __saturatef(r1 * vm);
        r2 = __saturatef(r2 * vm);
        r0 = fex2(gamma * flg2(r0)); // 0 -> ex2(-inf) = 0 == 0^g
        r1 = fex2(gamma * flg2(r1));
        r2 = fex2(gamma * flg2(r2));

        float o0 = __saturatef(c0 * r0 + c1 * r1 + c2 * r2);
        float o1 = __saturatef(c3 * r0 + c4 * r1 + c5 * r2);
        float o2 = __saturatef(c6 * r0 + c7 * r1 + c8 * r2);

        bool cut = cutx & (fabsf(fiy - ccy_px) < chh_px);
        if (cut) { o0 = 0.f; o1 = 0.f; o2 = 0.f; }

        float* op = out + outBase;
        op[0] = o0;
        op[1] = o1;
        op[2] = o2;

        Y += cc;
        fiy += 1.f;
        outBase += W_ * 3;
    }
}

extern "C" void kernel_launch(void* const* d_in, const int* in_sizes, int n_in,
                              void* d_out, int out_size) {
    const float* images   = (const float*)d_in[0];
    const float* geom_u   = (const float*)d_in[1];
    const float* color_u  = (const float*)d_in[2];
    const float* cutout_u = (const float*)d_in[3];
    float* out = (float*)d_out;

    param_kernel<<<1, 32>>>(geom_u, color_u, cutout_u);
    dim3 grid(W_ / 32, H_ / 32, B_);
    augment_main<<<grid, NT>>>(images, out);
}